// round 5
// baseline (speedup 1.0000x reference)
#include <cuda_runtime.h>

// Problem constants (fixed shapes from the reference setup_inputs)
#define Bq   4
#define Tq   512
#define TPq  1024
#define Cq   32
#define Kq   128
#define EPSF 2.2204460492503131e-16f

// Scratch (__device__ globals — no allocation allowed in kernel_launch)
__device__ float g_sp_alpha[Cq * Cq];   // softplus(alpha)[e][c]
__device__ float g_sp_delta[Cq * Cq];   // softplus(delta)[e][c] + EPS
__device__ float g_sp_mu[Cq];
__device__ float g_probs[Kq];           // p(fine k | coarse ftc[k])
// Prefix table: G[b][j][e][c], j in [0, T]  (8.4 MB)
__device__ float g_table[(size_t)Bq * (Tq + 1) * Cq * Cq];

__device__ __forceinline__ float softplus_f(float x) {
    // log(1 + e^x), numerically stable; matches jax.nn.softplus within fp32 noise
    return (x > 0.0f) ? x + log1pf(expf(-x)) : log1pf(expf(x));
}

// ---------------------------------------------------------------------------
// Kernel 1: parameter prep (tiny)
// ---------------------------------------------------------------------------
__global__ void prep_kernel(const float* __restrict__ mu,
                            const float* __restrict__ alpha,
                            const float* __restrict__ delta,
                            const float* __restrict__ cf,
                            const int*   __restrict__ ftc) {
    int tid = threadIdx.x;
    if (tid < Cq * Cq) {
        g_sp_alpha[tid] = softplus_f(alpha[tid]);
        g_sp_delta[tid] = softplus_f(delta[tid]) + EPSF;
    }
    if (tid < Cq) g_sp_mu[tid] = softplus_f(mu[tid]);
    if (tid == 0) {
        // grouped softmax over fine logits (K=128, C=32) — trivial, serial
        float m = cf[0];
        for (int k = 1; k < Kq; k++) m = fmaxf(m, cf[k]);
        float ev[Kq];
        float denom[Cq];
        for (int c = 0; c < Cq; c++) denom[c] = 0.0f;
        for (int k = 0; k < Kq; k++) { ev[k] = expf(cf[k] - m); denom[ftc[k]] += ev[k]; }
        for (int k = 0; k < Kq; k++) g_probs[k] = ev[k] / denom[ftc[k]];
    }
}

// ---------------------------------------------------------------------------
// Kernel 2: build causal prefix table
//   block = (b, e) pair, 32 threads (lane = channel c)
//   G[b][j][e][c] = sum over events i<j with type e of pa[e,c]*exp(pd[e,c]*pt_i)
// ---------------------------------------------------------------------------
__global__ void table_kernel(const int*   __restrict__ past_event,
                             const float* __restrict__ past_time) {
    int b = blockIdx.x / Cq;
    int e = blockIdx.x % Cq;
    int c = threadIdx.x;

    __shared__ int   s_ev[Tq];
    __shared__ float s_pt[Tq];
    for (int i = c; i < Tq; i += 32) {
        s_ev[i] = past_event[b * Tq + i];
        s_pt[i] = past_time[b * Tq + i];
    }
    __syncthreads();

    float pa = g_sp_alpha[e * Cq + c];
    float pd = g_sp_delta[e * Cq + c];
    float run = 0.0f;

    float* out = g_table + ((size_t)b * (Tq + 1)) * (Cq * Cq) + e * Cq + c;
    #pragma unroll 8
    for (int j = 0; j < Tq; j++) {
        out[(size_t)j * (Cq * Cq)] = run;
        if (s_ev[j] == e) run += pa * __expf(pd * s_pt[j]);
    }
    out[(size_t)Tq * (Cq * Cq)] = run;
}

// ---------------------------------------------------------------------------
// Kernel 3: queries. One warp per query time.
//   acc[c] = sp_mu[c] + sum_e exp(-pd[e,c]*t') * G[b][j][e][c]
//   out[k] = acc[ftc[k]] * p[k]
// ---------------------------------------------------------------------------
#define QPB 8   // queries (warps) per block -> 256 threads
__global__ void query_kernel(const float* __restrict__ time_tensor,
                             const float* __restrict__ past_time,
                             const int*   __restrict__ ftc,
                             float*       __restrict__ out) {
    const int blocks_per_b = TPq / QPB;
    int b    = blockIdx.x / blocks_per_b;
    int q0   = (blockIdx.x % blocks_per_b) * QPB;
    int wid  = threadIdx.x >> 5;
    int lane = threadIdx.x & 31;

    __shared__ float s_pt[Tq];
    __shared__ float s_pd[Cq * Cq];
    __shared__ float s_mu[Cq];
    __shared__ float s_p[Kq];
    __shared__ int   s_ftc[Kq];
    __shared__ float s_acc[QPB][Cq];

    for (int i = threadIdx.x; i < Tq; i += blockDim.x) s_pt[i] = past_time[b * Tq + i];
    for (int i = threadIdx.x; i < Cq * Cq; i += blockDim.x) s_pd[i] = g_sp_delta[i];
    if (threadIdx.x < Cq) s_mu[threadIdx.x] = g_sp_mu[threadIdx.x];
    for (int i = threadIdx.x; i < Kq; i += blockDim.x) {
        s_p[i]   = g_probs[i];
        s_ftc[i] = ftc[i];
    }
    __syncthreads();

    int   tp = q0 + wid;
    float t  = time_tensor[b * TPq + tp];

    // binary search: j = #{i : t - pt_i > EPS}  (pt non-decreasing)
    int lo = 0, hi = Tq;
    while (lo < hi) {
        int mid = (lo + hi) >> 1;
        if (t - s_pt[mid] > EPSF) lo = mid + 1; else hi = mid;
    }

    const float* Grow = g_table + (((size_t)b * (Tq + 1) + lo) * Cq) * Cq;

    float acc = s_mu[lane];
    #pragma unroll
    for (int e = 0; e < Cq; e++) {
        acc = fmaf(__expf(-s_pd[e * Cq + lane] * t), Grow[e * Cq + lane], acc);
    }
    s_acc[wid][lane] = acc;
    __syncwarp();

    float* o = out + ((size_t)(b * TPq + tp)) * Kq;
    #pragma unroll
    for (int kk = lane; kk < Kq; kk += 32) {
        o[kk] = s_acc[wid][s_ftc[kk]] * s_p[kk];
    }
}

// ---------------------------------------------------------------------------
// Launch: 3 graph-capturable kernel launches, no sync, no allocation.
// Input order (metadata): past_event, past_time, time_tensor, mu, alpha,
//                         delta, cf_logits, ftc
// ---------------------------------------------------------------------------
extern "C" void kernel_launch(void* const* d_in, const int* in_sizes, int n_in,
                              void* d_out, int out_size) {
    (void)in_sizes; (void)n_in; (void)out_size;
    const int*   past_event  = (const int*)  d_in[0];
    const float* past_time   = (const float*)d_in[1];
    const float* time_tensor = (const float*)d_in[2];
    const float* mu          = (const float*)d_in[3];
    const float* alpha       = (const float*)d_in[4];
    const float* delta       = (const float*)d_in[5];
    const float* cf          = (const float*)d_in[6];
    const int*   ftc         = (const int*)  d_in[7];
    float*       out         = (float*)d_out;

    prep_kernel<<<1, 1024>>>(mu, alpha, delta, cf, ftc);
    table_kernel<<<Bq * Cq, 32>>>(past_event, past_time);
    query_kernel<<<Bq * (TPq / QPB), 32 * QPB>>>(time_tensor, past_time, ftc, out);
}

// round 6
// speedup vs baseline: 3.2949x; 3.2949x over previous
#include <cuda_runtime.h>

// Problem constants (fixed shapes from the reference setup_inputs)
#define Bq   4
#define Tq   512
#define TPq  1024
#define Cq   32
#define Kq   128
#define EPSF 2.2204460492503131e-16f

// Scratch (__device__ globals — no allocation allowed in kernel_launch)
__device__ float g_sp_delta[Cq * Cq];   // softplus(delta)[e][c] + EPS
__device__ float g_sp_mu[Cq];
__device__ float g_probs[Kq];           // p(fine k | coarse ftc[k])
// Prefix table: G[b][j][e][c], j in [0, T]  (8.4 MB)
__device__ float g_table[(size_t)Bq * (Tq + 1) * Cq * Cq];

__device__ __forceinline__ float softplus_f(float x) {
    // log(1 + e^x), numerically stable fast version (rel err ~1e-6, tol is 1e-3)
    return (x > 0.0f) ? x + __logf(1.0f + __expf(-x))
                      : __logf(1.0f + __expf(x));
}

// ---------------------------------------------------------------------------
// Kernel 1: build causal prefix table + publish prepped parameters.
//   block = (b, e) pair, 128 threads = 4 warps; lane = channel c,
//   warp w owns j-chunk [w*128, (w+1)*128).
//   G[b][j][e][c] = sum over events i<j with type e of pa[e,c]*exp(pd[e,c]*pt_i)
//   Two-pass chunk scan: pass 1 chunk totals, pass 2 write prefix.
//   Side duties (replaces the old prep_kernel):
//     blocks with b==0, warp 0:  write g_sp_delta row e
//     block (0,0), warp 1:       write g_sp_mu
//     block (0,0), warp 2:       grouped softmax -> g_probs
// ---------------------------------------------------------------------------
__global__ void table_kernel(const int*   __restrict__ past_event,
                             const float* __restrict__ past_time,
                             const float* __restrict__ alpha,
                             const float* __restrict__ delta,
                             const float* __restrict__ mu,
                             const float* __restrict__ cf,
                             const int*   __restrict__ ftc) {
    int b   = blockIdx.x / Cq;
    int e   = blockIdx.x % Cq;
    int wid = threadIdx.x >> 5;
    int c   = threadIdx.x & 31;

    __shared__ int   s_ev[Tq];
    __shared__ float s_pt[Tq];
    __shared__ float s_chunk[4][Cq];
    __shared__ float s_den[Cq];

    for (int i = threadIdx.x; i < Tq; i += blockDim.x) {
        s_ev[i] = past_event[b * Tq + i];
        s_pt[i] = past_time[b * Tq + i];
    }

    float pa = softplus_f(alpha[e * Cq + c]);
    float pd = softplus_f(delta[e * Cq + c]) + EPSF;

    // ---- side duties (run before first __syncthreads, fully parallel) ----
    if (b == 0 && wid == 0) g_sp_delta[e * Cq + c] = pd;
    if (blockIdx.x == 0) {
        if (wid == 1) g_sp_mu[c] = softplus_f(mu[c]);
        if (wid == 2) {
            // grouped softmax over 128 fine logits (max-shift cancels exactly)
            s_den[c] = 0.0f;
            __syncwarp();
            float ev[4]; int fc[4];
            #pragma unroll
            for (int r = 0; r < 4; r++) {
                int k = r * 32 + c;
                ev[r] = __expf(cf[k]);
                fc[r] = ftc[k];
                atomicAdd(&s_den[fc[r]], ev[r]);
            }
            __syncwarp();
            #pragma unroll
            for (int r = 0; r < 4; r++)
                g_probs[r * 32 + c] = ev[r] / s_den[fc[r]];
        }
    }
    __syncthreads();

    const int CHUNK = Tq / 4;           // 128
    int j0 = wid * CHUNK, j1 = j0 + CHUNK;

    // pass 1: chunk totals
    float sum = 0.0f;
    for (int j = j0; j < j1; j++)
        if (s_ev[j] == e) sum += pa * __expf(pd * s_pt[j]);
    s_chunk[wid][c] = sum;
    __syncthreads();

    float off = 0.0f;
    #pragma unroll
    for (int w = 0; w < 4; w++) if (w < wid) off += s_chunk[w][c];

    // pass 2: write exclusive prefix
    float* out = g_table + ((size_t)b * (Tq + 1)) * (Cq * Cq) + e * Cq + c;
    float run = off;
    for (int j = j0; j < j1; j++) {
        out[(size_t)j * (Cq * Cq)] = run;
        if (s_ev[j] == e) run += pa * __expf(pd * s_pt[j]);
    }
    if (wid == 3) out[(size_t)Tq * (Cq * Cq)] = run;
}

// ---------------------------------------------------------------------------
// Kernel 2: queries. One warp per query time.
//   acc[c] = sp_mu[c] + sum_e exp(-pd[e,c]*t') * G[b][j][e][c]
//   out[k] = acc[ftc[k]] * p[k]
// ---------------------------------------------------------------------------
#define QPB 16   // queries (warps) per block -> 512 threads
__global__ void query_kernel(const float* __restrict__ time_tensor,
                             const float* __restrict__ past_time,
                             const int*   __restrict__ ftc,
                             float*       __restrict__ out) {
    const int blocks_per_b = TPq / QPB;
    int b    = blockIdx.x / blocks_per_b;
    int q0   = (blockIdx.x % blocks_per_b) * QPB;
    int wid  = threadIdx.x >> 5;
    int lane = threadIdx.x & 31;

    __shared__ float s_pt[Tq];
    __shared__ float s_pd[Cq * Cq];
    __shared__ float s_mu[Cq];
    __shared__ float s_p[Kq];
    __shared__ int   s_ftc[Kq];
    __shared__ float s_acc[QPB][Cq];

    for (int i = threadIdx.x; i < Tq; i += blockDim.x) s_pt[i] = past_time[b * Tq + i];
    for (int i = threadIdx.x; i < Cq * Cq; i += blockDim.x) s_pd[i] = g_sp_delta[i];
    if (threadIdx.x < Cq) s_mu[threadIdx.x] = g_sp_mu[threadIdx.x];
    for (int i = threadIdx.x; i < Kq; i += blockDim.x) {
        s_p[i]   = g_probs[i];
        s_ftc[i] = ftc[i];
    }
    __syncthreads();

    int   tp = q0 + wid;
    float t  = time_tensor[b * TPq + tp];

    // binary search: j = #{i : t - pt_i > EPS}  (pt non-decreasing)
    int lo = 0, hi = Tq;
    while (lo < hi) {
        int mid = (lo + hi) >> 1;
        if (t - s_pt[mid] > EPSF) lo = mid + 1; else hi = mid;
    }

    const float* Grow = g_table + (((size_t)b * (Tq + 1) + lo) * Cq) * Cq;

    float acc = s_mu[lane];
    #pragma unroll
    for (int e = 0; e < Cq; e++) {
        acc = fmaf(__expf(-s_pd[e * Cq + lane] * t), Grow[e * Cq + lane], acc);
    }
    s_acc[wid][lane] = acc;
    __syncwarp();

    float* o = out + ((size_t)(b * TPq + tp)) * Kq;
    #pragma unroll
    for (int kk = lane; kk < Kq; kk += 32) {
        o[kk] = s_acc[wid][s_ftc[kk]] * s_p[kk];
    }
}

// ---------------------------------------------------------------------------
// Launch: 2 graph-capturable kernel launches, no sync, no allocation.
// Input order (metadata): past_event, past_time, time_tensor, mu, alpha,
//                         delta, cf_logits, ftc
// ---------------------------------------------------------------------------
extern "C" void kernel_launch(void* const* d_in, const int* in_sizes, int n_in,
                              void* d_out, int out_size) {
    (void)in_sizes; (void)n_in; (void)out_size;
    const int*   past_event  = (const int*)  d_in[0];
    const float* past_time   = (const float*)d_in[1];
    const float* time_tensor = (const float*)d_in[2];
    const float* mu          = (const float*)d_in[3];
    const float* alpha       = (const float*)d_in[4];
    const float* delta       = (const float*)d_in[5];
    const float* cf          = (const float*)d_in[6];
    const int*   ftc         = (const int*)  d_in[7];
    float*       out         = (float*)d_out;

    table_kernel<<<Bq * Cq, 128>>>(past_event, past_time, alpha, delta, mu, cf, ftc);
    query_kernel<<<Bq * (TPq / QPB), 32 * QPB>>>(time_tensor, past_time, ftc, out);
}

// round 7
// speedup vs baseline: 3.7727x; 1.1450x over previous
#include <cuda_runtime.h>

// Problem constants (fixed shapes from the reference setup_inputs)
#define Bq   4
#define Tq   512
#define TPq  1024
#define Cq   32
#define Kq   128
#define EPSF 2.2204460492503131e-16f

// Scratch (__device__ globals — no allocation allowed in kernel_launch)
__device__ float g_sp_delta[Cq * Cq];   // softplus(delta)[e][c] + EPS
__device__ float g_sp_mu[Cq];
__device__ float g_probs[Kq];           // p(fine k | coarse ftc[k])
// Prefix table: G[b][j][e][c], j in [0, T]  (8.4 MB, L2-resident)
__device__ float g_table[(size_t)Bq * (Tq + 1) * Cq * Cq];

__device__ __forceinline__ float softplus_f(float x) {
    // log(1 + e^x), fast version (rel err ~1e-6, tol is 1e-3)
    return (x > 0.0f) ? x + __logf(1.0f + __expf(-x))
                      : __logf(1.0f + __expf(x));
}

// ---------------------------------------------------------------------------
// Kernel 1: build causal prefix table + publish prepped parameters.
//   block = (b, e) pair, 256 threads = 8 warps; lane = channel c,
//   warp w owns j-chunk [w*64, (w+1)*64).
//   G[b][j][e][c] = sum over events i<j with type e of pa[e,c]*exp(pd[e,c]*pt_i)
//   Two-pass chunk scan: pass 1 chunk totals, pass 2 write prefix.
//   Side duties (prep):  b==0,wid==0: g_sp_delta row e
//                        block 0, wid 1: g_sp_mu;  wid 2: grouped softmax
// ---------------------------------------------------------------------------
__global__ void __launch_bounds__(256)
table_kernel(const int*   __restrict__ past_event,
             const float* __restrict__ past_time,
             const float* __restrict__ alpha,
             const float* __restrict__ delta,
             const float* __restrict__ mu,
             const float* __restrict__ cf,
             const int*   __restrict__ ftc) {
    int b   = blockIdx.x / Cq;
    int e   = blockIdx.x % Cq;
    int wid = threadIdx.x >> 5;
    int c   = threadIdx.x & 31;

    __shared__ int   s_ev[Tq];
    __shared__ float s_pt[Tq];
    __shared__ float s_chunk[8][Cq];
    __shared__ float s_den[Cq];

    for (int i = threadIdx.x; i < Tq; i += blockDim.x) {
        s_ev[i] = past_event[b * Tq + i];
        s_pt[i] = past_time[b * Tq + i];
    }

    float pa = softplus_f(alpha[e * Cq + c]);
    float pd = softplus_f(delta[e * Cq + c]) + EPSF;

    // ---- side duties (before first __syncthreads, fully parallel) ----
    if (b == 0 && wid == 0) g_sp_delta[e * Cq + c] = pd;
    if (blockIdx.x == 0) {
        if (wid == 1) g_sp_mu[c] = softplus_f(mu[c]);
        if (wid == 2) {
            // grouped softmax over 128 fine logits (max-shift cancels exactly)
            s_den[c] = 0.0f;
            __syncwarp();
            float ev[4]; int fc[4];
            #pragma unroll
            for (int r = 0; r < 4; r++) {
                int k = r * 32 + c;
                ev[r] = __expf(cf[k]);
                fc[r] = ftc[k];
                atomicAdd(&s_den[fc[r]], ev[r]);
            }
            __syncwarp();
            #pragma unroll
            for (int r = 0; r < 4; r++)
                g_probs[r * 32 + c] = ev[r] / s_den[fc[r]];
        }
    }
    __syncthreads();

    const int CHUNK = Tq / 8;           // 64
    int j0 = wid * CHUNK, j1 = j0 + CHUNK;

    // pass 1: chunk totals (s_ev[j]==e is warp-uniform -> exp only on matches)
    float sum = 0.0f;
    for (int j = j0; j < j1; j++)
        if (s_ev[j] == e) sum += pa * __expf(pd * s_pt[j]);
    s_chunk[wid][c] = sum;
    __syncthreads();

    float off = 0.0f;
    #pragma unroll
    for (int w = 0; w < 8; w++) if (w < wid) off += s_chunk[w][c];

    // pass 2: write exclusive prefix
    float* out = g_table + ((size_t)b * (Tq + 1)) * (Cq * Cq) + e * Cq + c;
    float run = off;
    for (int j = j0; j < j1; j++) {
        out[(size_t)j * (Cq * Cq)] = run;
        if (s_ev[j] == e) run += pa * __expf(pd * s_pt[j]);
    }
    if (wid == 7) out[(size_t)Tq * (Cq * Cq)] = run;
}

// ---------------------------------------------------------------------------
// Kernel 2: queries. One warp per query time. NO shared memory, NO barriers.
//   acc[c] = sp_mu[c] + sum_e exp(-pd[e,c]*t') * G[b][j][e][c]
//   out[k] = acc[ftc[k]] * p[k]          (gather via warp shuffle)
// ---------------------------------------------------------------------------
__global__ void __launch_bounds__(128, 8)
query_kernel(const float* __restrict__ time_tensor,
             const float* __restrict__ past_time,
             const int*   __restrict__ ftc,
             float*       __restrict__ out) {
    int warp_g = (blockIdx.x * blockDim.x + threadIdx.x) >> 5;  // global query id
    int lane   = threadIdx.x & 31;
    int b      = warp_g / TPq;

    float t = time_tensor[warp_g];

    // binary search: j = #{i : t - pt_i > EPS}  (pt non-decreasing).
    // Warp-uniform index -> one broadcast load per step, L1-hot after warmup.
    const float* pt = past_time + b * Tq;
    int lo = 0, hi = Tq;
    while (lo < hi) {
        int mid = (lo + hi) >> 1;
        if (t - __ldg(&pt[mid]) > EPSF) lo = mid + 1; else hi = mid;
    }

    const float* Grow = g_table + ((size_t)(b * (Tq + 1) + lo)) * (Cq * Cq);

    // Precompute all 32 decay factors (independent MUFU ops, pipelined)
    float ex[Cq];
    #pragma unroll
    for (int e = 0; e < Cq; e++)
        ex[e] = __expf(-__ldg(&g_sp_delta[e * Cq + lane]) * t);

    // 32 independent coalesced L2 loads + 4-way FMA trees
    float a0 = 0.0f, a1 = 0.0f, a2 = 0.0f, a3 = 0.0f;
    #pragma unroll
    for (int e = 0; e < Cq; e += 4) {
        a0 = fmaf(ex[e + 0], __ldg(&Grow[(e + 0) * Cq + lane]), a0);
        a1 = fmaf(ex[e + 1], __ldg(&Grow[(e + 1) * Cq + lane]), a1);
        a2 = fmaf(ex[e + 2], __ldg(&Grow[(e + 2) * Cq + lane]), a2);
        a3 = fmaf(ex[e + 3], __ldg(&Grow[(e + 3) * Cq + lane]), a3);
    }
    float acc = ((a0 + a1) + (a2 + a3)) + __ldg(&g_sp_mu[lane]);

    // Output: out[k] = acc[ftc[k]] * p[k], gather via shuffle (no smem)
    float* o = out + (size_t)warp_g * Kq;
    #pragma unroll
    for (int r = 0; r < 4; r++) {
        int   kk = r * 32 + lane;
        int   fc = __ldg(&ftc[kk]);
        float av = __shfl_sync(0xffffffffu, acc, fc);
        o[kk] = av * __ldg(&g_probs[kk]);
    }
}

// ---------------------------------------------------------------------------
// Launch: 2 graph-capturable kernel launches, no sync, no allocation.
// Input order (metadata): past_event, past_time, time_tensor, mu, alpha,
//                         delta, cf_logits, ftc
// ---------------------------------------------------------------------------
extern "C" void kernel_launch(void* const* d_in, const int* in_sizes, int n_in,
                              void* d_out, int out_size) {
    (void)in_sizes; (void)n_in; (void)out_size;
    const int*   past_event  = (const int*)  d_in[0];
    const float* past_time   = (const float*)d_in[1];
    const float* time_tensor = (const float*)d_in[2];
    const float* mu          = (const float*)d_in[3];
    const float* alpha       = (const float*)d_in[4];
    const float* delta       = (const float*)d_in[5];
    const float* cf          = (const float*)d_in[6];
    const int*   ftc         = (const int*)  d_in[7];
    float*       out         = (float*)d_out;

    table_kernel<<<Bq * Cq, 256>>>(past_event, past_time, alpha, delta, mu, cf, ftc);
    // 4096 queries, 1 warp each, 128-thread blocks -> 1024 blocks
    query_kernel<<<(Bq * TPq) / 4, 128>>>(time_tensor, past_time, ftc, out);
}